// round 1
// baseline (speedup 1.0000x reference)
#include <cuda_runtime.h>

#define BS   4
#define V    4096
#define NB   32
#define CIN  128
#define COUT 256
#define NROWS (BS*V)        // 16384 distinct (b,u) feature rows
#define NSAMP (BS*V*NB)     // 524288 samples for BN stats

// -------- scratch (device globals; no allocations allowed) --------
__device__ float g_F[NROWS * CIN];     // 8 MB  : [fmap | L2-dist] per (b,u)
__device__ float g_Z[NROWS * COUT];    // 16 MB : F @ W^T + b, then relu(BN) in-place
__device__ int   g_cnt[NROWS];         // histogram of neighbor indices
__device__ float g_sum[COUT];
__device__ float g_sq[COUT];
__device__ float g_a[COUT];            // gamma * rstd
__device__ float g_d[COUT];            // beta - mean * gamma * rstd

// -------- K0: zero accumulators (graph replays must be deterministic) --------
__global__ void k_zero() {
    int i = blockIdx.x * blockDim.x + threadIdx.x;
    if (i < NROWS) g_cnt[i] = 0;
    if (i < COUT) { g_sum[i] = 0.0f; g_sq[i] = 0.0f; }
}

// -------- K1: F[b,u] = concat(fmap[b,u,0:127], ||fmap[b,u]||)  (1 warp/row) --------
__global__ void k_feat(const float* __restrict__ fmap) {
    int warp = (blockIdx.x * blockDim.x + threadIdx.x) >> 5;
    int lane = threadIdx.x & 31;
    if (warp >= NROWS) return;
    const float* src = fmap + (size_t)warp * (CIN - 1);
    float v0 = src[lane];
    float v1 = src[lane + 32];
    float v2 = src[lane + 64];
    float v3 = (lane + 96 < CIN - 1) ? src[lane + 96] : 0.0f;
    float ss = v0*v0 + v1*v1 + v2*v2 + v3*v3;
    #pragma unroll
    for (int o = 16; o; o >>= 1) ss += __shfl_xor_sync(0xffffffffu, ss, o);
    float* dst = g_F + (size_t)warp * CIN;
    dst[lane] = v0; dst[lane + 32] = v1; dst[lane + 64] = v2;
    if (lane + 96 < CIN - 1) dst[lane + 96] = v3;
    if (lane == 31) dst[CIN - 1] = sqrtf(ss);
}

// -------- K2: histogram of neighbor indices (weights for BN stats) --------
__global__ void k_hist(const int* __restrict__ idx) {
    int i = blockIdx.x * blockDim.x + threadIdx.x;
    if (i >= NSAMP) return;
    int b = i >> 17;                    // V*NB = 131072 = 2^17 per batch
    atomicAdd(&g_cnt[(b << 12) + idx[i]], 1);
}

// -------- K3: Z = F @ W^T + bias  (fp32, 128x128 tile, K=128 resident) --------
__global__ __launch_bounds__(256) void k_gemm(const float* __restrict__ Wm,
                                              const float* __restrict__ bias) {
    extern __shared__ float sh[];
    float* Fs = sh;                 // [k][m]  128*128
    float* Ws = sh + 128 * 128;     // [k][n]  128*128
    int t = threadIdx.x;
    int mbase = blockIdx.x * 128;
    int nbase = blockIdx.y * 128;

    // load + transpose into shared (STS conflict-free: consecutive m per warp)
    {
        int m    = t & 127;
        int half = t >> 7;   // 0/1 -> k range [half*64, half*64+64)
        const float4* fg = (const float4*)(g_F + (size_t)(mbase + m) * CIN);
        const float4* wg = (const float4*)(Wm  + (size_t)(nbase + m) * CIN);
        #pragma unroll
        for (int q = 0; q < 16; q++) {
            int k4 = half * 64 + q * 4;
            float4 a  = fg[k4 >> 2];
            Fs[(k4+0)*128 + m] = a.x;  Fs[(k4+1)*128 + m] = a.y;
            Fs[(k4+2)*128 + m] = a.z;  Fs[(k4+3)*128 + m] = a.w;
            float4 bb = wg[k4 >> 2];
            Ws[(k4+0)*128 + m] = bb.x; Ws[(k4+1)*128 + m] = bb.y;
            Ws[(k4+2)*128 + m] = bb.z; Ws[(k4+3)*128 + m] = bb.w;
        }
    }
    __syncthreads();

    int tx = t & 15, ty = t >> 4;
    int rm0 = tx * 4, rm1 = 64 + tx * 4;
    int cn0 = ty * 4, cn1 = 64 + ty * 4;
    float acc[8][8];
    #pragma unroll
    for (int i = 0; i < 8; i++)
        #pragma unroll
        for (int j = 0; j < 8; j++) acc[i][j] = 0.0f;

    #pragma unroll 4
    for (int k = 0; k < 128; k++) {
        float4 a0 = *(const float4*)&Fs[k*128 + rm0];
        float4 a1 = *(const float4*)&Fs[k*128 + rm1];
        float4 b0 = *(const float4*)&Ws[k*128 + cn0];
        float4 b1 = *(const float4*)&Ws[k*128 + cn1];
        float av[8] = {a0.x,a0.y,a0.z,a0.w, a1.x,a1.y,a1.z,a1.w};
        float bv[8] = {b0.x,b0.y,b0.z,b0.w, b1.x,b1.y,b1.z,b1.w};
        #pragma unroll
        for (int i = 0; i < 8; i++)
            #pragma unroll
            for (int j = 0; j < 8; j++)
                acc[i][j] = fmaf(av[i], bv[j], acc[i][j]);
    }

    #pragma unroll
    for (int i = 0; i < 8; i++) {
        int m = mbase + (i < 4 ? rm0 + i : rm1 + i - 4);
        float* zr = g_Z + (size_t)m * COUT + nbase;
        #pragma unroll
        for (int jj = 0; jj < 2; jj++) {
            int cn = (jj == 0 ? cn0 : cn1);
            float4 o;
            o.x = acc[i][jj*4+0] + __ldg(&bias[nbase + cn + 0]);
            o.y = acc[i][jj*4+1] + __ldg(&bias[nbase + cn + 1]);
            o.z = acc[i][jj*4+2] + __ldg(&bias[nbase + cn + 2]);
            o.w = acc[i][jj*4+3] + __ldg(&bias[nbase + cn + 3]);
            *(float4*)&zr[cn] = o;
        }
    }
}

// -------- K4: weighted per-channel sums of Z and Z^2 --------
__global__ void k_stats() {
    int c  = threadIdx.x;            // 256 channels
    int r0 = blockIdx.x * 64;        // 256 blocks x 64 rows
    float s = 0.0f, q = 0.0f;
    #pragma unroll 4
    for (int r = 0; r < 64; r++) {
        float w = (float)g_cnt[r0 + r];
        float z = g_Z[(size_t)(r0 + r) * COUT + c];
        s = fmaf(w, z, s);
        q = fmaf(w * z, z, q);
    }
    atomicAdd(&g_sum[c], s);
    atomicAdd(&g_sq[c], q);
}

// -------- K5: BN affine params --------
__global__ void k_params(const float* __restrict__ gamma, const float* __restrict__ beta) {
    int c = threadIdx.x;
    const float invN = 1.0f / (float)NSAMP;
    float mean = g_sum[c] * invN;
    float var  = fmaxf(g_sq[c] * invN - mean * mean, 0.0f);
    float a    = gamma[c] / sqrtf(var + 1e-5f);
    g_a[c] = a;
    g_d[c] = beta[c] - mean * a;
}

// -------- K6: Z <- relu(Z * a + d)  (in place) --------
__global__ void k_norm() {
    int i = blockIdx.x * blockDim.x + threadIdx.x;     // float4 index
    float4* Z4 = (float4*)g_Z;
    int c0 = (i * 4) & (COUT - 1);
    float4 z = Z4[i];
    z.x = fmaxf(fmaf(z.x, g_a[c0+0], g_d[c0+0]), 0.0f);
    z.y = fmaxf(fmaf(z.y, g_a[c0+1], g_d[c0+1]), 0.0f);
    z.z = fmaxf(fmaf(z.z, g_a[c0+2], g_d[c0+2]), 0.0f);
    z.w = fmaxf(fmaf(z.w, g_a[c0+3], g_d[c0+3]), 0.0f);
    Z4[i] = z;
}

// -------- K7: fused theta * relu(zn), max over 32 neighbors --------
__global__ __launch_bounds__(64) void k_final(const int* __restrict__ idx,
                                              const float* __restrict__ verts,
                                              const float* __restrict__ dirs,
                                              float* __restrict__ out) {
    __shared__ float4 sh[NB];        // (wx, wy, wz, bitcast u) per neighbor
    int row = blockIdx.x;            // b*V + v
    int b   = row >> 12;
    int t   = threadIdx.x;
    if (t < NB) {
        int u = idx[(size_t)row * NB + t];
        const float* nv = verts + (size_t)((b << 12) + u) * 3;
        const float* cv = verts + (size_t)row * 3;
        float dx = nv[0] - cv[0], dy = nv[1] - cv[1], dz = nv[2] - cv[2];
        float nrm = sqrtf(dx*dx + dy*dy + dz*dz);
        float inv = 1.0f / fmaxf(nrm, 1e-12f);
        sh[t] = make_float4(fmaf(dx*inv, 0.5f, 0.5f),
                            fmaf(dy*inv, 0.5f, 0.5f),
                            fmaf(dz*inv, 0.5f, 0.5f),
                            __int_as_float(u));
    }
    __syncthreads();

    int c0 = t * 4;
    float4 r0 = *(const float4*)&dirs[c0];
    float4 r1 = *(const float4*)&dirs[COUT + c0];
    float4 r2 = *(const float4*)&dirs[2*COUT + c0];
    float4 r3 = *(const float4*)&dirs[3*COUT + c0];
    float4 s1 = make_float4(r1.x-r0.x, r1.y-r0.y, r1.z-r0.z, r1.w-r0.w);
    float4 s2 = make_float4(r2.x-r0.x, r2.y-r0.y, r2.z-r0.z, r2.w-r0.w);
    float4 s3 = make_float4(r3.x-r0.x, r3.y-r0.y, r3.z-r0.z, r3.w-r0.w);
    float4 acc = make_float4(0.f, 0.f, 0.f, 0.f);   // relu(zn)>=0 and theta>=0

    #pragma unroll
    for (int n = 0; n < NB; n++) {
        float4 wv = sh[n];
        int u = __float_as_int(wv.w);
        float4 zr = *(const float4*)&g_Z[(size_t)((b << 12) + u) * COUT + c0];
        float th;
        th = fmaxf(fmaf(wv.x, s1.x, fmaf(wv.y, s2.x, fmaf(wv.z, s3.x, r0.x))), 0.f);
        acc.x = fmaxf(acc.x, zr.x * th);
        th = fmaxf(fmaf(wv.x, s1.y, fmaf(wv.y, s2.y, fmaf(wv.z, s3.y, r0.y))), 0.f);
        acc.y = fmaxf(acc.y, zr.y * th);
        th = fmaxf(fmaf(wv.x, s1.z, fmaf(wv.y, s2.z, fmaf(wv.z, s3.z, r0.z))), 0.f);
        acc.z = fmaxf(acc.z, zr.z * th);
        th = fmaxf(fmaf(wv.x, s1.w, fmaf(wv.y, s2.w, fmaf(wv.z, s3.w, r0.w))), 0.f);
        acc.w = fmaxf(acc.w, zr.w * th);
    }
    *(float4*)&out[(size_t)row * COUT + c0] = acc;
}

extern "C" void kernel_launch(void* const* d_in, const int* in_sizes, int n_in,
                              void* d_out, int out_size) {
    const int*   idx   = (const int*)d_in[0];
    const float* verts = (const float*)d_in[1];
    const float* fmap  = (const float*)d_in[2];
    const float* dirs  = (const float*)d_in[3];
    const float* Wm    = (const float*)d_in[4];
    const float* bias  = (const float*)d_in[5];
    const float* gamma = (const float*)d_in[6];
    const float* beta  = (const float*)d_in[7];
    float* out = (float*)d_out;

    k_zero<<<(NROWS + 255) / 256, 256>>>();
    k_feat<<<NROWS / 4, 128>>>(fmap);
    k_hist<<<NSAMP / 256, 256>>>(idx);

    cudaFuncSetAttribute(k_gemm, cudaFuncAttributeMaxDynamicSharedMemorySize, 131072);
    k_gemm<<<dim3(NROWS / 128, COUT / 128), 256, 131072>>>(Wm, bias);

    k_stats<<<NROWS / 64, 256>>>();
    k_params<<<1, 256>>>(gamma, beta);
    k_norm<<<(NROWS * COUT / 4) / 256, 256>>>();
    k_final<<<NROWS, 64>>>(idx, verts, dirs, out);
}

// round 4
// speedup vs baseline: 1.4242x; 1.4242x over previous
#include <cuda_runtime.h>
#include <cuda_bf16.h>
#include <cuda_fp16.h>
#include <cstdint>

#define BS   4
#define V    4096
#define NB   32
#define CIN  128
#define COUT 256
#define NROWS (BS*V)        // 16384 distinct (b,u) rows
#define NSAMP (BS*V*NB)     // 524288 samples for BN stats
#define KP    384           // split-K: [hi | lo | hi]
#define KSTEPS (KP/16)      // 24 mma k-steps
#define SLD   (KP + 8)      // padded smem row stride (392 bf16 -> conflict-free ldmatrix)

// -------- scratch (device globals; no allocations allowed) --------
__device__ __align__(16) __nv_bfloat16 g_A2[NROWS * KP];   // 12.6 MB
__device__ __align__(16) __nv_bfloat16 g_B2[COUT * KP];    // 192 KB
__device__ __align__(16) float  g_Z [NROWS * COUT];        // 16 MB  raw z
__device__ __align__(16) __half g_Zh[NROWS * COUT];        // 8 MB   relu(BN(z)) fp16
__device__ int   g_cnt[NROWS];
__device__ float g_sum[COUT], g_sq[COUT], g_a[COUT], g_d[COUT];

static __device__ __forceinline__ uint32_t smem_u32(const void* p) {
    uint32_t a;
    asm("{ .reg .u64 t; cvta.to.shared.u64 t, %1; cvt.u32.u64 %0, t; }"
        : "=r"(a) : "l"(p));
    return a;
}
static __device__ __forceinline__ void ldsm_x4(uint32_t* r, uint32_t addr) {
    asm volatile("ldmatrix.sync.aligned.m8n8.x4.shared.b16 {%0,%1,%2,%3}, [%4];"
                 : "=r"(r[0]), "=r"(r[1]), "=r"(r[2]), "=r"(r[3]) : "r"(addr));
}
static __device__ __forceinline__ void mma_bf16(float* c, const uint32_t* a,
                                                uint32_t b0, uint32_t b1) {
    asm volatile(
        "mma.sync.aligned.m16n8k16.row.col.f32.bf16.bf16.f32 "
        "{%0,%1,%2,%3}, {%4,%5,%6,%7}, {%8,%9}, {%0,%1,%2,%3};"
        : "+f"(c[0]), "+f"(c[1]), "+f"(c[2]), "+f"(c[3])
        : "r"(a[0]), "r"(a[1]), "r"(a[2]), "r"(a[3]), "r"(b0), "r"(b1));
}

// -------- K0: zero accumulators (graph replays must be deterministic) --------
__global__ void k_zero() {
    int i = blockIdx.x * blockDim.x + threadIdx.x;
    if (i < NROWS) g_cnt[i] = 0;
    if (i < COUT) { g_sum[i] = 0.0f; g_sq[i] = 0.0f; }
}

// -------- K1: A' rows = [hi(F) | lo(F) | hi(F)], F = [fmap, ||fmap||] --------
__global__ void k_feat(const float* __restrict__ fmap) {
    int warp = (blockIdx.x * blockDim.x + threadIdx.x) >> 5;
    int lane = threadIdx.x & 31;
    if (warp >= NROWS) return;
    const float* src = fmap + (size_t)warp * (CIN - 1);
    float v0 = src[lane];
    float v1 = src[lane + 32];
    float v2 = src[lane + 64];
    float v3 = (lane < 31) ? src[lane + 96] : 0.0f;
    float ss = v0*v0 + v1*v1 + v2*v2 + v3*v3;
    #pragma unroll
    for (int o = 16; o; o >>= 1) ss += __shfl_xor_sync(0xffffffffu, ss, o);
    if (lane == 31) v3 = sqrtf(ss);          // channel 127 = L2 distance
    __nv_bfloat16* dst = g_A2 + (size_t)warp * KP;
    float vv[4] = {v0, v1, v2, v3};
    #pragma unroll
    for (int q = 0; q < 4; q++) {
        int c = lane + q * 32;
        __nv_bfloat16 h = __float2bfloat16_rn(vv[q]);
        __nv_bfloat16 l = __float2bfloat16_rn(vv[q] - __bfloat162float(h));
        dst[c] = h; dst[c + 128] = l; dst[c + 256] = h;
    }
}

// -------- K1b: B' rows = [hi(W) | hi(W) | lo(W)] --------
__global__ void k_prepB(const float* __restrict__ Wm) {
    int n = threadIdx.x;               // one thread per output channel
    __nv_bfloat16* dst = g_B2 + (size_t)n * KP;
    const float* src = Wm + (size_t)n * CIN;
    for (int k = 0; k < CIN; k++) {
        float w = src[k];
        __nv_bfloat16 h = __float2bfloat16_rn(w);
        __nv_bfloat16 l = __float2bfloat16_rn(w - __bfloat162float(h));
        dst[k] = h; dst[k + 128] = h; dst[k + 256] = l;
    }
}

// -------- K2: histogram of neighbor indices --------
__global__ void k_hist(const int* __restrict__ idx) {
    int i = blockIdx.x * blockDim.x + threadIdx.x;
    if (i >= NSAMP) return;
    int b = i >> 17;                    // V*NB = 2^17 per batch
    atomicAdd(&g_cnt[(b << 12) + idx[i]], 1);
}

// -------- K3: HMMA GEMM  Z = A' @ B'^T + bias  (bf16 mma.sync, fp32 accum) ----
// CTA 128x128, full K'=384 in smem (padded stride), 8 warps of 64x32.
__global__ __launch_bounds__(256) void k_gemm_mma(const float* __restrict__ bias) {
    extern __shared__ __nv_bfloat16 sm[];
    __nv_bfloat16* As = sm;                  // [128][SLD]
    __nv_bfloat16* Bs = sm + 128 * SLD;      // [128][SLD]
    int tid = threadIdx.x, wid = tid >> 5, lane = tid & 31;
    int mbase = blockIdx.x * 128, nbase = blockIdx.y * 128;

    // cooperative tile load (uint4 = 8 bf16), 48 chunks/row
    {
        const uint4* Ag = (const uint4*)(g_A2 + (size_t)mbase * KP);
        const uint4* Bg = (const uint4*)(g_B2 + (size_t)nbase * KP);
        #pragma unroll
        for (int i = tid; i < 128 * 48; i += 256) {
            int r = i / 48, c = i % 48;
            *(uint4*)&As[r * SLD + c * 8] = Ag[r * 48 + c];
            *(uint4*)&Bs[r * SLD + c * 8] = Bg[r * 48 + c];
        }
    }
    __syncthreads();

    int warp_m = (wid >> 2) * 64;            // 2 warp-rows
    int warp_n = (wid & 3) * 32;             // 4 warp-cols
    uint32_t sb = smem_u32(sm);
    // ldmatrix per-thread addresses (element offsets, x2 bytes)
    uint32_t aaddr = sb + (uint32_t)(((warp_m + (lane & 15)) * SLD + (lane >> 4) * 8) * 2);
    uint32_t baddr = sb + (uint32_t)((128 * SLD
                     + (warp_n + ((lane >> 4) & 1) * 8 + (lane & 7)) * SLD
                     + ((lane >> 3) & 1) * 8) * 2);

    float acc[4][4][4];
    #pragma unroll
    for (int mi = 0; mi < 4; mi++)
        #pragma unroll
        for (int ni = 0; ni < 4; ni++)
            #pragma unroll
            for (int q = 0; q < 4; q++) acc[mi][ni][q] = 0.0f;

    #pragma unroll 2
    for (int ks = 0; ks < KSTEPS; ks++) {
        uint32_t koff = (uint32_t)(ks * 16 * 2);     // bytes along k
        uint32_t a[4][4], b[2][4];
        #pragma unroll
        for (int mi = 0; mi < 4; mi++)
            ldsm_x4(a[mi], aaddr + (uint32_t)(mi * 16 * SLD * 2) + koff);
        #pragma unroll
        for (int nj = 0; nj < 2; nj++)
            ldsm_x4(b[nj], baddr + (uint32_t)(nj * 16 * SLD * 2) + koff);
        #pragma unroll
        for (int mi = 0; mi < 4; mi++)
            #pragma unroll
            for (int ni = 0; ni < 4; ni++)
                mma_bf16(acc[mi][ni], a[mi],
                         b[ni >> 1][(ni & 1) * 2], b[ni >> 1][(ni & 1) * 2 + 1]);
    }

    // epilogue: c frag (m16n8): rows t/4 and t/4+8, cols 2*(t&3)
    int r0 = lane >> 2, c0 = (lane & 3) * 2;
    #pragma unroll
    for (int mi = 0; mi < 4; mi++) {
        #pragma unroll
        for (int ni = 0; ni < 4; ni++) {
            int col = nbase + warp_n + ni * 8 + c0;
            float bx = __ldg(&bias[col]), by = __ldg(&bias[col + 1]);
            int rowA = mbase + warp_m + mi * 16 + r0;
            float2 o0 = make_float2(acc[mi][ni][0] + bx, acc[mi][ni][1] + by);
            *(float2*)&g_Z[(size_t)rowA * COUT + col] = o0;
            float2 o1 = make_float2(acc[mi][ni][2] + bx, acc[mi][ni][3] + by);
            *(float2*)&g_Z[(size_t)(rowA + 8) * COUT + col] = o1;
        }
    }
}

// -------- K4: weighted per-channel sums of Z and Z^2 --------
__global__ void k_stats() {
    int c  = threadIdx.x;            // 256 channels
    int r0 = blockIdx.x * 64;        // 256 blocks x 64 rows
    float s = 0.0f, q = 0.0f;
    #pragma unroll 4
    for (int r = 0; r < 64; r++) {
        float w = (float)g_cnt[r0 + r];
        float z = g_Z[(size_t)(r0 + r) * COUT + c];
        s = fmaf(w, z, s);
        q = fmaf(w * z, z, q);
    }
    atomicAdd(&g_sum[c], s);
    atomicAdd(&g_sq[c], q);
}

// -------- K5: BN affine params --------
__global__ void k_params(const float* __restrict__ gamma, const float* __restrict__ beta) {
    int c = threadIdx.x;
    const float invN = 1.0f / (float)NSAMP;
    float mean = g_sum[c] * invN;
    float var  = fmaxf(g_sq[c] * invN - mean * mean, 0.0f);
    float a    = gamma[c] / sqrtf(var + 1e-5f);
    g_a[c] = a;
    g_d[c] = beta[c] - mean * a;
}

// -------- K6: Zh <- fp16(relu(Z * a + d)) --------
__global__ void k_norm() {
    int i = blockIdx.x * blockDim.x + threadIdx.x;     // float4 index
    const float4* Z4 = (const float4*)g_Z;
    int c0 = (i * 4) & (COUT - 1);
    float4 z = Z4[i];
    z.x = fmaxf(fmaf(z.x, g_a[c0+0], g_d[c0+0]), 0.0f);
    z.y = fmaxf(fmaf(z.y, g_a[c0+1], g_d[c0+1]), 0.0f);
    z.z = fmaxf(fmaf(z.z, g_a[c0+2], g_d[c0+2]), 0.0f);
    z.w = fmaxf(fmaf(z.w, g_a[c0+3], g_d[c0+3]), 0.0f);
    __half2 h01 = __floats2half2_rn(z.x, z.y);
    __half2 h23 = __floats2half2_rn(z.z, z.w);
    uint2 o;
    o.x = *reinterpret_cast<unsigned*>(&h01);
    o.y = *reinterpret_cast<unsigned*>(&h23);
    ((uint2*)g_Zh)[i] = o;
}

// -------- K7: fused theta * relu(zn), max over 32 neighbors (fp16 gather) ----
__global__ __launch_bounds__(64) void k_final(const int* __restrict__ idx,
                                              const float* __restrict__ verts,
                                              const float* __restrict__ dirs,
                                              float* __restrict__ out) {
    __shared__ float4 sh[NB];        // (wx, wy, wz, bitcast u)
    int row = blockIdx.x;            // b*V + v
    int b   = row >> 12;
    int t   = threadIdx.x;
    if (t < NB) {
        int u = idx[(size_t)row * NB + t];
        const float* nv = verts + (size_t)((b << 12) + u) * 3;
        const float* cv = verts + (size_t)row * 3;
        float dx = nv[0] - cv[0], dy = nv[1] - cv[1], dz = nv[2] - cv[2];
        float nrm = sqrtf(dx*dx + dy*dy + dz*dz);
        float inv = 1.0f / fmaxf(nrm, 1e-12f);
        sh[t] = make_float4(fmaf(dx*inv, 0.5f, 0.5f),
                            fmaf(dy*inv, 0.5f, 0.5f),
                            fmaf(dz*inv, 0.5f, 0.5f),
                            __int_as_float(u));
    }
    __syncthreads();

    int c0 = t * 4;
    float4 r0 = *(const float4*)&dirs[c0];
    float4 r1 = *(const float4*)&dirs[COUT + c0];
    float4 r2 = *(const float4*)&dirs[2*COUT + c0];
    float4 r3 = *(const float4*)&dirs[3*COUT + c0];
    float4 s1 = make_float4(r1.x-r0.x, r1.y-r0.y, r1.z-r0.z, r1.w-r0.w);
    float4 s2 = make_float4(r2.x-r0.x, r2.y-r0.y, r2.z-r0.z, r2.w-r0.w);
    float4 s3 = make_float4(r3.x-r0.x, r3.y-r0.y, r3.z-r0.z, r3.w-r0.w);
    float4 acc = make_float4(0.f, 0.f, 0.f, 0.f);   // relu(zn)>=0 and theta>=0

    #pragma unroll
    for (int n = 0; n < NB; n++) {
        float4 wv = sh[n];
        int u = __float_as_int(wv.w);
        uint2 p = *(const uint2*)&g_Zh[(size_t)((b << 12) + u) * COUT + c0];
        float2 z01 = __half22float2(*reinterpret_cast<__half2*>(&p.x));
        float2 z23 = __half22float2(*reinterpret_cast<__half2*>(&p.y));
        float th;
        th = fmaxf(fmaf(wv.x, s1.x, fmaf(wv.y, s2.x, fmaf(wv.z, s3.x, r0.x))), 0.f);
        acc.x = fmaxf(acc.x, z01.x * th);
        th = fmaxf(fmaf(wv.x, s1.y, fmaf(wv.y, s2.y, fmaf(wv.z, s3.y, r0.y))), 0.f);
        acc.y = fmaxf(acc.y, z01.y * th);
        th = fmaxf(fmaf(wv.x, s1.z, fmaf(wv.y, s2.z, fmaf(wv.z, s3.z, r0.z))), 0.f);
        acc.z = fmaxf(acc.z, z23.x * th);
        th = fmaxf(fmaf(wv.x, s1.w, fmaf(wv.y, s2.w, fmaf(wv.z, s3.w, r0.w))), 0.f);
        acc.w = fmaxf(acc.w, z23.y * th);
    }
    *(float4*)&out[(size_t)row * COUT + c0] = acc;
}

extern "C" void kernel_launch(void* const* d_in, const int* in_sizes, int n_in,
                              void* d_out, int out_size) {
    const int*   idx   = (const int*)d_in[0];
    const float* verts = (const float*)d_in[1];
    const float* fmap  = (const float*)d_in[2];
    const float* dirs  = (const float*)d_in[3];
    const float* Wm    = (const float*)d_in[4];
    const float* bias  = (const float*)d_in[5];
    const float* gamma = (const float*)d_in[6];
    const float* beta  = (const float*)d_in[7];
    float* out = (float*)d_out;

    k_zero<<<(NROWS + 255) / 256, 256>>>();
    k_feat<<<NROWS / 4, 128>>>(fmap);
    k_prepB<<<1, COUT>>>(Wm);
    k_hist<<<NSAMP / 256, 256>>>(idx);

    const int smem = 2 * 128 * SLD * (int)sizeof(__nv_bfloat16);   // 200704 B
    cudaFuncSetAttribute(k_gemm_mma, cudaFuncAttributeMaxDynamicSharedMemorySize, smem);
    k_gemm_mma<<<dim3(NROWS / 128, COUT / 128), 256, smem>>>(bias);

    k_stats<<<NROWS / 64, 256>>>();
    k_params<<<1, 256>>>(gamma, beta);
    k_norm<<<(NROWS * COUT / 4) / 256, 256>>>();
    k_final<<<NROWS, 64>>>(idx, verts, dirs, out);
}

// round 5
// speedup vs baseline: 1.7642x; 1.2388x over previous
#include <cuda_runtime.h>
#include <cuda_bf16.h>
#include <cuda_fp16.h>
#include <cstdint>

#define BS   4
#define V    4096
#define NB   32
#define CIN  128
#define COUT 256
#define NROWS (BS*V)        // 16384 distinct (b,u) rows
#define NSAMP (BS*V*NB)     // 524288 samples for BN stats
#define KP    384           // split-K: [hi | lo | hi]
#define KSTEPS (KP/16)      // 24 mma k-steps
#define SLD   (KP + 8)      // padded smem row stride (392 bf16 -> conflict-free ldmatrix)

// k_prep block-role partition
#define NFEAT_BLK 2048      // 8 rows/block (8 warps)
#define NPREPB_BLK 16       // 16 rows/block
#define NHIST_BLK 32        // 16384 samples/block, smem-privatized
#define PREP_GRID (NFEAT_BLK + NPREPB_BLK + NHIST_BLK)

// -------- scratch (device globals; no allocations allowed) --------
__device__ __align__(16) __nv_bfloat16 g_A2[NROWS * KP];   // 12.6 MB
__device__ __align__(16) __nv_bfloat16 g_B2[COUT * KP];    // 192 KB
__device__ __align__(16) float  g_Z [NROWS * COUT];        // 16 MB  raw z
__device__ __align__(16) __half g_Zh[NROWS * COUT];        // 8 MB   relu(BN(z)) fp16
__device__ int   g_cnt[NROWS];
__device__ float g_sum[COUT], g_sq[COUT];

static __device__ __forceinline__ uint32_t smem_u32(const void* p) {
    uint32_t a;
    asm("{ .reg .u64 t; cvta.to.shared.u64 t, %1; cvt.u32.u64 %0, t; }"
        : "=r"(a) : "l"(p));
    return a;
}
static __device__ __forceinline__ void ldsm_x4(uint32_t* r, uint32_t addr) {
    asm volatile("ldmatrix.sync.aligned.m8n8.x4.shared.b16 {%0,%1,%2,%3}, [%4];"
                 : "=r"(r[0]), "=r"(r[1]), "=r"(r[2]), "=r"(r[3]) : "r"(addr));
}
static __device__ __forceinline__ void mma_bf16(float* c, const uint32_t* a,
                                                uint32_t b0, uint32_t b1) {
    asm volatile(
        "mma.sync.aligned.m16n8k16.row.col.f32.bf16.bf16.f32 "
        "{%0,%1,%2,%3}, {%4,%5,%6,%7}, {%8,%9}, {%0,%1,%2,%3};"
        : "+f"(c[0]), "+f"(c[1]), "+f"(c[2]), "+f"(c[3])
        : "r"(a[0]), "r"(a[1]), "r"(a[2]), "r"(a[3]), "r"(b0), "r"(b1));
}

// -------- K0: zero accumulators (graph replays must be deterministic) --------
__global__ void k_zero() {
    int i = blockIdx.x * blockDim.x + threadIdx.x;
    if (i < NROWS) g_cnt[i] = 0;
    if (i < COUT) { g_sum[i] = 0.0f; g_sq[i] = 0.0f; }
}

// -------- K1: fused prep: feat (A') + prepB (B') + idx histogram --------
__global__ __launch_bounds__(256) void k_prep(const float* __restrict__ fmap,
                                              const float* __restrict__ Wm,
                                              const int* __restrict__ idx) {
    int blk = blockIdx.x;
    int tid = threadIdx.x;

    if (blk < NFEAT_BLK) {
        // ---- feat: A' rows = [hi(F) | lo(F) | hi(F)], F = [fmap, ||fmap||] ----
        int warp = blk * 8 + (tid >> 5);
        int lane = tid & 31;
        const float* src = fmap + (size_t)warp * (CIN - 1);
        float v0 = src[lane];
        float v1 = src[lane + 32];
        float v2 = src[lane + 64];
        float v3 = (lane < 31) ? src[lane + 96] : 0.0f;
        float ss = v0*v0 + v1*v1 + v2*v2 + v3*v3;
        #pragma unroll
        for (int o = 16; o; o >>= 1) ss += __shfl_xor_sync(0xffffffffu, ss, o);
        if (lane == 31) v3 = sqrtf(ss);      // channel 127 = L2 distance
        __nv_bfloat16* dst = g_A2 + (size_t)warp * KP;
        float vv[4] = {v0, v1, v2, v3};
        #pragma unroll
        for (int q = 0; q < 4; q++) {
            int c = lane + q * 32;
            __nv_bfloat16 h = __float2bfloat16_rn(vv[q]);
            __nv_bfloat16 l = __float2bfloat16_rn(vv[q] - __bfloat162float(h));
            dst[c] = h; dst[c + 128] = l; dst[c + 256] = h;
        }
    } else if (blk < NFEAT_BLK + NPREPB_BLK) {
        // ---- prepB: B' rows = [hi(W) | hi(W) | lo(W)] ----
        int base = (blk - NFEAT_BLK) * 16;       // 16 rows per block
        for (int i = tid; i < 16 * CIN; i += 256) {
            int n = base + (i >> 7);
            int k = i & 127;
            float w = Wm[(size_t)n * CIN + k];
            __nv_bfloat16 h = __float2bfloat16_rn(w);
            __nv_bfloat16 l = __float2bfloat16_rn(w - __bfloat162float(h));
            __nv_bfloat16* dst = g_B2 + (size_t)n * KP;
            dst[k] = h; dst[k + 128] = h; dst[k + 256] = l;
        }
    } else {
        // ---- hist: smem-privatized histogram over 16384 samples ----
        __shared__ int scnt[V];
        int hb = blk - NFEAT_BLK - NPREPB_BLK;   // 0..31
        int batch = hb >> 3;
        #pragma unroll
        for (int j = tid; j < V; j += 256) scnt[j] = 0;
        __syncthreads();
        const int4* src = (const int4*)(idx + (size_t)batch * (V * NB) + (hb & 7) * 16384);
        #pragma unroll 4
        for (int it = 0; it < 16; it++) {
            int4 v = src[it * 256 + tid];
            atomicAdd(&scnt[v.x], 1);
            atomicAdd(&scnt[v.y], 1);
            atomicAdd(&scnt[v.z], 1);
            atomicAdd(&scnt[v.w], 1);
        }
        __syncthreads();
        for (int j = tid; j < V; j += 256) {
            int c = scnt[j];
            if (c) atomicAdd(&g_cnt[(batch << 12) + j], c);
        }
    }
}

// -------- K2: HMMA GEMM  Z = A' @ B'^T + bias, fused weighted BN stats --------
// CTA 128x128, full K'=384 in smem (padded stride), 8 warps of 64x32.
__global__ __launch_bounds__(256) void k_gemm_mma(const float* __restrict__ bias) {
    extern __shared__ __nv_bfloat16 sm[];
    __nv_bfloat16* As = sm;                  // [128][SLD]
    __nv_bfloat16* Bs = sm + 128 * SLD;      // [128][SLD]
    int tid = threadIdx.x, wid = tid >> 5, lane = tid & 31;
    int mbase = blockIdx.x * 128, nbase = blockIdx.y * 128;

    // cooperative tile load (uint4 = 8 bf16), 48 chunks/row
    {
        const uint4* Ag = (const uint4*)(g_A2 + (size_t)mbase * KP);
        const uint4* Bg = (const uint4*)(g_B2 + (size_t)nbase * KP);
        #pragma unroll
        for (int i = tid; i < 128 * 48; i += 256) {
            int r = i / 48, c = i % 48;
            *(uint4*)&As[r * SLD + c * 8] = Ag[r * 48 + c];
            *(uint4*)&Bs[r * SLD + c * 8] = Bg[r * 48 + c];
        }
    }
    __syncthreads();

    int warp_m = (wid >> 2) * 64;            // 2 warp-rows
    int warp_n = (wid & 3) * 32;             // 4 warp-cols
    uint32_t sb = smem_u32(sm);
    uint32_t aaddr = sb + (uint32_t)(((warp_m + (lane & 15)) * SLD + (lane >> 4) * 8) * 2);
    uint32_t baddr = sb + (uint32_t)((128 * SLD
                     + (warp_n + ((lane >> 4) & 1) * 8 + (lane & 7)) * SLD
                     + ((lane >> 3) & 1) * 8) * 2);

    float acc[4][4][4];
    #pragma unroll
    for (int mi = 0; mi < 4; mi++)
        #pragma unroll
        for (int ni = 0; ni < 4; ni++)
            #pragma unroll
            for (int q = 0; q < 4; q++) acc[mi][ni][q] = 0.0f;

    #pragma unroll 2
    for (int ks = 0; ks < KSTEPS; ks++) {
        uint32_t koff = (uint32_t)(ks * 16 * 2);
        uint32_t a[4][4], b[2][4];
        #pragma unroll
        for (int mi = 0; mi < 4; mi++)
            ldsm_x4(a[mi], aaddr + (uint32_t)(mi * 16 * SLD * 2) + koff);
        #pragma unroll
        for (int nj = 0; nj < 2; nj++)
            ldsm_x4(b[nj], baddr + (uint32_t)(nj * 16 * SLD * 2) + koff);
        #pragma unroll
        for (int mi = 0; mi < 4; mi++)
            #pragma unroll
            for (int ni = 0; ni < 4; ni++)
                mma_bf16(acc[mi][ni], a[mi],
                         b[ni >> 1][(ni & 1) * 2], b[ni >> 1][(ni & 1) * 2 + 1]);
    }

    // ---- epilogue: tiles no longer needed; reuse smem for stats ----
    __syncthreads();
    float* ssum = (float*)sm;        // [128]
    float* ssq  = ssum + 128;        // [128]
    if (tid < 128) ssum[tid] = 0.0f;
    else if (tid < 256) ssq[tid - 128] = 0.0f;
    __syncthreads();

    int r0 = lane >> 2, c0 = (lane & 3) * 2;
    // per-mi row weights (counts)
    float wlo[4], whi[4];
    #pragma unroll
    for (int mi = 0; mi < 4; mi++) {
        int rowA = mbase + warp_m + mi * 16 + r0;
        wlo[mi] = (float)__ldg(&g_cnt[rowA]);
        whi[mi] = (float)__ldg(&g_cnt[rowA + 8]);
    }
    #pragma unroll
    for (int ni = 0; ni < 4; ni++) {
        int coll = warp_n + ni * 8 + c0;             // 0..127 local col
        int col  = nbase + coll;
        float bx = __ldg(&bias[col]), by = __ldg(&bias[col + 1]);
        float sx = 0.f, qx = 0.f, sy = 0.f, qy = 0.f;
        #pragma unroll
        for (int mi = 0; mi < 4; mi++) {
            int rowA = mbase + warp_m + mi * 16 + r0;
            float v0 = acc[mi][ni][0] + bx, v1 = acc[mi][ni][1] + by;
            float v2 = acc[mi][ni][2] + bx, v3 = acc[mi][ni][3] + by;
            *(float2*)&g_Z[(size_t)rowA * COUT + col] = make_float2(v0, v1);
            *(float2*)&g_Z[(size_t)(rowA + 8) * COUT + col] = make_float2(v2, v3);
            sx = fmaf(wlo[mi], v0, sx); qx = fmaf(wlo[mi] * v0, v0, qx);
            sx = fmaf(whi[mi], v2, sx); qx = fmaf(whi[mi] * v2, v2, qx);
            sy = fmaf(wlo[mi], v1, sy); qy = fmaf(wlo[mi] * v1, v1, qy);
            sy = fmaf(whi[mi], v3, sy); qy = fmaf(whi[mi] * v3, v3, qy);
        }
        atomicAdd(&ssum[coll], sx);     atomicAdd(&ssq[coll], qx);
        atomicAdd(&ssum[coll + 1], sy); atomicAdd(&ssq[coll + 1], qy);
    }
    __syncthreads();
    if (tid < 128)      atomicAdd(&g_sum[nbase + tid], ssum[tid]);
    else if (tid < 256) atomicAdd(&g_sq[nbase + tid - 128], ssq[tid - 128]);
}

// -------- K3: Zh <- fp16(relu(Z * a + d)), BN params computed inline --------
__global__ __launch_bounds__(256) void k_norm(const float* __restrict__ gamma,
                                              const float* __restrict__ beta) {
    __shared__ float sa[COUT], sd[COUT];
    int t = threadIdx.x;
    {
        const float invN = 1.0f / (float)NSAMP;
        float mean = g_sum[t] * invN;
        float var  = fmaxf(g_sq[t] * invN - mean * mean, 0.0f);
        float a    = gamma[t] / sqrtf(var + 1e-5f);
        sa[t] = a;
        sd[t] = beta[t] - mean * a;
    }
    __syncthreads();

    int i = blockIdx.x * 256 + t;                    // float4 index
    const float4* Z4 = (const float4*)g_Z;
    int c0 = (i * 4) & (COUT - 1);
    float4 z = Z4[i];
    z.x = fmaxf(fmaf(z.x, sa[c0+0], sd[c0+0]), 0.0f);
    z.y = fmaxf(fmaf(z.y, sa[c0+1], sd[c0+1]), 0.0f);
    z.z = fmaxf(fmaf(z.z, sa[c0+2], sd[c0+2]), 0.0f);
    z.w = fmaxf(fmaf(z.w, sa[c0+3], sd[c0+3]), 0.0f);
    __half2 h01 = __floats2half2_rn(z.x, z.y);
    __half2 h23 = __floats2half2_rn(z.z, z.w);
    uint2 o;
    o.x = *reinterpret_cast<unsigned*>(&h01);
    o.y = *reinterpret_cast<unsigned*>(&h23);
    ((uint2*)g_Zh)[i] = o;
}

// -------- K4: fused theta * relu(zn), max over 32 neighbors (2 rows/block) --
__global__ __launch_bounds__(128) void k_final(const int* __restrict__ idx,
                                               const float* __restrict__ verts,
                                               const float* __restrict__ dirs,
                                               float* __restrict__ out) {
    __shared__ float4 sh[2][NB];     // (wx, wy, wz, bitcast u)
    int half = threadIdx.x >> 6;     // 0/1 -> which row
    int t    = threadIdx.x & 63;
    int row  = blockIdx.x * 2 + half;
    int b    = row >> 12;
    if (t < NB) {
        int u = idx[(size_t)row * NB + t];
        const float* nv = verts + (size_t)((b << 12) + u) * 3;
        const float* cv = verts + (size_t)row * 3;
        float dx = nv[0] - cv[0], dy = nv[1] - cv[1], dz = nv[2] - cv[2];
        float nrm = sqrtf(dx*dx + dy*dy + dz*dz);
        float inv = 1.0f / fmaxf(nrm, 1e-12f);
        sh[half][t] = make_float4(fmaf(dx*inv, 0.5f, 0.5f),
                                  fmaf(dy*inv, 0.5f, 0.5f),
                                  fmaf(dz*inv, 0.5f, 0.5f),
                                  __int_as_float(u));
    }
    __syncthreads();

    int c0 = t * 4;
    float4 r0 = *(const float4*)&dirs[c0];
    float4 r1 = *(const float4*)&dirs[COUT + c0];
    float4 r2 = *(const float4*)&dirs[2*COUT + c0];
    float4 r3 = *(const float4*)&dirs[3*COUT + c0];
    float4 s1 = make_float4(r1.x-r0.x, r1.y-r0.y, r1.z-r0.z, r1.w-r0.w);
    float4 s2 = make_float4(r2.x-r0.x, r2.y-r0.y, r2.z-r0.z, r2.w-r0.w);
    float4 s3 = make_float4(r3.x-r0.x, r3.y-r0.y, r3.z-r0.z, r3.w-r0.w);
    float4 acc = make_float4(0.f, 0.f, 0.f, 0.f);   // relu(zn)>=0 and theta>=0

    #pragma unroll
    for (int n = 0; n < NB; n++) {
        float4 wv = sh[half][n];
        int u = __float_as_int(wv.w);
        uint2 p = *(const uint2*)&g_Zh[(size_t)((b << 12) + u) * COUT + c0];
        float2 z01 = __half22float2(*reinterpret_cast<__half2*>(&p.x));
        float2 z23 = __half22float2(*reinterpret_cast<__half2*>(&p.y));
        float th;
        th = fmaxf(fmaf(wv.x, s1.x, fmaf(wv.y, s2.x, fmaf(wv.z, s3.x, r0.x))), 0.f);
        acc.x = fmaxf(acc.x, z01.x * th);
        th = fmaxf(fmaf(wv.x, s1.y, fmaf(wv.y, s2.y, fmaf(wv.z, s3.y, r0.y))), 0.f);
        acc.y = fmaxf(acc.y, z01.y * th);
        th = fmaxf(fmaf(wv.x, s1.z, fmaf(wv.y, s2.z, fmaf(wv.z, s3.z, r0.z))), 0.f);
        acc.z = fmaxf(acc.z, z23.x * th);
        th = fmaxf(fmaf(wv.x, s1.w, fmaf(wv.y, s2.w, fmaf(wv.z, s3.w, r0.w))), 0.f);
        acc.w = fmaxf(acc.w, z23.y * th);
    }
    *(float4*)&out[(size_t)row * COUT + c0] = acc;
}

extern "C" void kernel_launch(void* const* d_in, const int* in_sizes, int n_in,
                              void* d_out, int out_size) {
    const int*   idx   = (const int*)d_in[0];
    const float* verts = (const float*)d_in[1];
    const float* fmap  = (const float*)d_in[2];
    const float* dirs  = (const float*)d_in[3];
    const float* Wm    = (const float*)d_in[4];
    const float* bias  = (const float*)d_in[5];
    const float* gamma = (const float*)d_in[6];
    const float* beta  = (const float*)d_in[7];
    float* out = (float*)d_out;

    k_zero<<<(NROWS + 255) / 256, 256>>>();
    k_prep<<<PREP_GRID, 256>>>(fmap, Wm, idx);

    const int smem = 2 * 128 * SLD * (int)sizeof(__nv_bfloat16);   // 200704 B
    cudaFuncSetAttribute(k_gemm_mma, cudaFuncAttributeMaxDynamicSharedMemorySize, smem);
    k_gemm_mma<<<dim3(NROWS / 128, COUT / 128), 256, smem>>>(bias);

    k_norm<<<NROWS * COUT / 4 / 256, 256>>>(gamma, beta);
    k_final<<<NROWS / 2, 128>>>(idx, verts, dirs, out);
}